// round 1
// baseline (speedup 1.0000x reference)
#include <cuda_runtime.h>
#include <math.h>
#include <stdint.h>

// ---------------------------------------------------------------------------
// FastKAN 3-layer conv net, fp32 SIMT baseline.
// Per layer:
//   1) prep:      3x3 patch gather + LayerNorm -> pn[N,fin]; silu(p) -> sp[N,fin]
//   2) wtrans:    interleave Wb/Ws into wt[K'=fin*9][fout]  (k = i*9 + t,
//                 t==0 -> silu/base weight, t=1..8 -> RBF grid j=t-1)
//   3) kan_gemm:  C[N,fout] = sum_k A[n,k]*wt[k,o] + bb[o], where A is
//                 generated on the fly: A[n,i*9]=sp, A[n,i*9+1+j]=exp(-((pn-g_j)*1.75)^2)
//   4) bn_stats:  per-channel sum/sumsq over N
//   5) bn_pool:   BN(batch stats) + ReLU + 2x2 maxpool -> next input (NCHW)
// ---------------------------------------------------------------------------

#define MAXF_PN   (131072 * 144)       // = 18,874,368 (max over layers of N*fin)
#define MAXF_WT   (1152 * 9 * 256)     // = 2,654,208
#define MAXF_CONV (131072 * 64)        // = 8,388,608
#define MAXF_X1   (32 * 64 * 32 * 32)  // = 2,097,152
#define MAXF_X2   (32 * 128 * 16 * 16) // =   524,288

__device__ float g_pn[MAXF_PN];
__device__ float g_sp[MAXF_PN];
__device__ float g_wt[MAXF_WT];
__device__ float g_conv[MAXF_CONV];
__device__ float g_x1[MAXF_X1];
__device__ float g_x2[MAXF_X2];
__device__ float g_bn[2 * 256];

// ---------------------------------------------------------------------------
// 1) patch gather + LayerNorm + SiLU.  One warp per output pixel.
// Patch feature order: f = c*9 + kh*3 + kw  (matches conv_general_dilated_patches)
// ---------------------------------------------------------------------------
__global__ void prep_kernel(const float* __restrict__ x,
                            const float* __restrict__ lnw,
                            const float* __restrict__ lnb,
                            float* __restrict__ pn, float* __restrict__ sp,
                            int C, int H, int W, int fin, int N)
{
    int warp = (blockIdx.x * blockDim.x + threadIdx.x) >> 5;
    int lane = threadIdx.x & 31;
    if (warp >= N) return;
    int w = warp % W;
    int h = (warp / W) % H;
    int b = warp / (W * H);
    const float* xb = x + (size_t)b * C * H * W;

    float s = 0.f, s2 = 0.f;
    for (int f = lane; f < fin; f += 32) {
        int c = f / 9, r = f - c * 9;
        int hh = h + r / 3 - 1, ww = w + (r % 3) - 1;
        float v = 0.f;
        if (hh >= 0 && hh < H && ww >= 0 && ww < W)
            v = xb[(c * H + hh) * W + ww];
        s += v; s2 += v * v;
    }
#pragma unroll
    for (int o = 16; o; o >>= 1) {
        s  += __shfl_xor_sync(0xffffffffu, s,  o);
        s2 += __shfl_xor_sync(0xffffffffu, s2, o);
    }
    float inv  = 1.f / (float)fin;
    float mu   = s * inv;
    float var  = fmaxf(s2 * inv - mu * mu, 0.f);
    float rstd = rsqrtf(var + 1e-5f);

    size_t base = (size_t)warp * fin;
    for (int f = lane; f < fin; f += 32) {
        int c = f / 9, r = f - c * 9;
        int hh = h + r / 3 - 1, ww = w + (r % 3) - 1;
        float v = 0.f;
        if (hh >= 0 && hh < H && ww >= 0 && ww < W)
            v = xb[(c * H + hh) * W + ww];
        pn[base + f] = (v - mu) * rstd * lnw[f] + lnb[f];
        sp[base + f] = v / (1.f + __expf(-v));     // silu
    }
}

// ---------------------------------------------------------------------------
// 2) weight interleave/transpose: wt[(i*9+t)*fout + o]
// ---------------------------------------------------------------------------
__global__ void wtrans_kernel(const float* __restrict__ Wb,
                              const float* __restrict__ Ws,
                              float* __restrict__ wt, int fin, int fout)
{
    int idx = blockIdx.x * blockDim.x + threadIdx.x;
    int total = fin * 9 * fout;
    if (idx >= total) return;
    int o  = idx % fout;
    int kk = idx / fout;
    int i  = kk / 9, t = kk - i * 9;
    float v = (t == 0) ? Wb[(size_t)o * fin + i]
                       : Ws[(size_t)o * fin * 8 + i * 8 + (t - 1)];
    wt[idx] = v;
}

// ---------------------------------------------------------------------------
// 3) fused KAN GEMM.  Tile: 128 rows x 64 cols, 256 threads, 8x4 per thread.
//    K chunk: 4 patch features -> 36 expanded basis rows in smem.
// ---------------------------------------------------------------------------
__global__ __launch_bounds__(256)
void kan_gemm_kernel(const float* __restrict__ pn, const float* __restrict__ sp,
                     const float* __restrict__ wt, const float* __restrict__ bb,
                     float* __restrict__ out, int N, int fin, int fout)
{
    __shared__ float pn_s[4][128];
    __shared__ float sp_s[4][128];
    __shared__ float bas[36][128];
    __shared__ float wts[36][64];

    int t  = threadIdx.x;
    int tx = t & 15;          // 16 col groups of 4
    int ty = t >> 4;          // 16 row groups of 8
    int row0 = blockIdx.x * 128;
    int ob   = blockIdx.y * 64;

    float acc[8][4];
#pragma unroll
    for (int r = 0; r < 8; r++)
#pragma unroll
        for (int c = 0; c < 4; c++) acc[r][c] = 0.f;

    for (int ib = 0; ib < fin; ib += 4) {
        __syncthreads();
        // ---- stage pn/sp chunk (4 features x 128 rows) ----
        if (t < 128) {
            float4 v = *(const float4*)&pn[(size_t)(row0 + t) * fin + ib];
            pn_s[0][t] = v.x; pn_s[1][t] = v.y; pn_s[2][t] = v.z; pn_s[3][t] = v.w;
        } else {
            int m = t - 128;
            float4 v = *(const float4*)&sp[(size_t)(row0 + m) * fin + ib];
            sp_s[0][m] = v.x; sp_s[1][m] = v.y; sp_s[2][m] = v.z; sp_s[3][m] = v.w;
        }
        // ---- stage weights (36 x 64) ----
        for (int e = t; e < 36 * 16; e += 256) {
            int kk = e >> 4, nseg = e & 15;
            float4 v = *(const float4*)&wt[(size_t)(ib * 9 + kk) * fout + ob + nseg * 4];
            *(float4*)&wts[kk][nseg * 4] = v;
        }
        __syncthreads();
        // ---- expand basis: silu + 8 gaussian RBF per (row, feature) ----
#pragma unroll
        for (int p = t; p < 512; p += 256) {
            int m  = p & 127;
            int il = p >> 7;
            float xv = pn_s[il][m];
            bas[il * 9][m] = sp_s[il][m];
#pragma unroll
            for (int j = 0; j < 8; j++) {
                float g  = -2.f + (float)j * (4.f / 7.f);
                float tt = (xv - g) * 1.75f;        // 1/DENOM = 7/4
                bas[il * 9 + 1 + j][m] = __expf(-tt * tt);
            }
        }
        __syncthreads();
        // ---- 128x64x36 micro-GEMM ----
#pragma unroll 4
        for (int kk = 0; kk < 36; kk++) {
            float4 a0 = *(const float4*)&bas[kk][ty * 8];
            float4 a1 = *(const float4*)&bas[kk][ty * 8 + 4];
            float4 b0 = *(const float4*)&wts[kk][tx * 4];
            float av[8] = {a0.x, a0.y, a0.z, a0.w, a1.x, a1.y, a1.z, a1.w};
            float bv[4] = {b0.x, b0.y, b0.z, b0.w};
#pragma unroll
            for (int r = 0; r < 8; r++)
#pragma unroll
                for (int c = 0; c < 4; c++)
                    acc[r][c] = fmaf(av[r], bv[c], acc[r][c]);
        }
    }

    float4 bv4 = *(const float4*)&bb[ob + tx * 4];
#pragma unroll
    for (int r = 0; r < 8; r++) {
        int n = row0 + ty * 8 + r;
        float4 o4;
        o4.x = acc[r][0] + bv4.x;
        o4.y = acc[r][1] + bv4.y;
        o4.z = acc[r][2] + bv4.z;
        o4.w = acc[r][3] + bv4.w;
        *(float4*)&out[(size_t)n * fout + ob + tx * 4] = o4;
    }
}

// ---------------------------------------------------------------------------
// 4) BN batch stats (sum, sumsq per channel)
// ---------------------------------------------------------------------------
__global__ void bn_stats_kernel(const float* __restrict__ conv,
                                float* __restrict__ bn,
                                int N, int fout, int rows_per_block)
{
    __shared__ float r1[256];
    __shared__ float r2[256];
    int t   = threadIdx.x;
    int o   = t % fout;
    int rl  = t / fout;
    int rpb = 256 / fout;
    int n0  = blockIdx.x * rows_per_block;
    int n1  = min(N, n0 + rows_per_block);
    float s = 0.f, s2 = 0.f;
    for (int n = n0 + rl; n < n1; n += rpb) {
        float v = conv[(size_t)n * fout + o];
        s += v; s2 += v * v;
    }
    r1[t] = s; r2[t] = s2;
    __syncthreads();
    for (int off = 128; off >= fout; off >>= 1) {
        if (t < off) { r1[t] += r1[t + off]; r2[t] += r2[t + off]; }
        __syncthreads();
    }
    if (t < fout) {
        atomicAdd(&bn[t],        r1[t]);
        atomicAdd(&bn[fout + t], r2[t]);
    }
}

// ---------------------------------------------------------------------------
// 5) BN apply + ReLU + 2x2 maxpool, output NCHW
// ---------------------------------------------------------------------------
__global__ void bn_pool_kernel(const float* __restrict__ conv,
                               const float* __restrict__ bn,
                               const float* __restrict__ gamma,
                               const float* __restrict__ beta,
                               float* __restrict__ xout,
                               int B, int fout, int H, int W)
{
    int H2 = H >> 1, W2 = W >> 1;
    int idx = blockIdx.x * blockDim.x + threadIdx.x;
    int total = B * fout * H2 * W2;
    if (idx >= total) return;
    int o = idx % fout;
    int r = idx / fout;
    int w2 = r % W2; r /= W2;
    int h2 = r % H2;
    int b  = r / H2;

    float cnt  = (float)(B * H * W);
    float mean = bn[o] / cnt;
    float var  = bn[fout + o] / cnt - mean * mean;
    float sc   = gamma[o] * rsqrtf(var + 1e-5f);
    float sh   = beta[o] - mean * sc;

    int h = h2 * 2, w = w2 * 2;
    size_t base = ((size_t)(b * H + h) * W + w) * fout + o;
    float v00 = conv[base];
    float v01 = conv[base + fout];
    float v10 = conv[base + (size_t)W * fout];
    float v11 = conv[base + (size_t)W * fout + fout];
    float m = fmaxf(fmaxf(fmaxf(v00 * sc + sh, 0.f), fmaxf(v01 * sc + sh, 0.f)),
                    fmaxf(fmaxf(v10 * sc + sh, 0.f), fmaxf(v11 * sc + sh, 0.f)));
    xout[((size_t)(b * fout + o) * H2 + h2) * W2 + w2] = m;
}

// ---------------------------------------------------------------------------
extern "C" void kernel_launch(void* const* d_in, const int* in_sizes, int n_in,
                              void* d_out, int out_size)
{
    (void)in_sizes; (void)n_in; (void)out_size;

    float *pn, *sp, *wt, *conv, *x1, *x2, *bn;
    cudaGetSymbolAddress((void**)&pn,   g_pn);
    cudaGetSymbolAddress((void**)&sp,   g_sp);
    cudaGetSymbolAddress((void**)&wt,   g_wt);
    cudaGetSymbolAddress((void**)&conv, g_conv);
    cudaGetSymbolAddress((void**)&x1,   g_x1);
    cudaGetSymbolAddress((void**)&x2,   g_x2);
    cudaGetSymbolAddress((void**)&bn,   g_bn);

    struct LCfg { int B, C, H, W, fin, fout; };
    const LCfg L[3] = {
        {32,  16, 64, 64,  144,  64},
        {32,  64, 32, 32,  576, 128},
        {32, 128, 16, 16, 1152, 256},
    };

    const float* xin = (const float*)d_in[0];
    for (int l = 0; l < 3; l++) {
        const float* lnw = (const float*)d_in[1 + 7 * l + 0];
        const float* lnb = (const float*)d_in[1 + 7 * l + 1];
        const float* Wb  = (const float*)d_in[1 + 7 * l + 2];
        const float* bbv = (const float*)d_in[1 + 7 * l + 3];
        const float* Ws  = (const float*)d_in[1 + 7 * l + 4];
        const float* gam = (const float*)d_in[1 + 7 * l + 5];
        const float* bet = (const float*)d_in[1 + 7 * l + 6];

        int B = L[l].B, C = L[l].C, H = L[l].H, W = L[l].W;
        int fin = L[l].fin, fout = L[l].fout;
        int N = B * H * W;

        prep_kernel<<<(N + 7) / 8, 256>>>(xin, lnw, lnb, pn, sp, C, H, W, fin, N);

        int wtot = fin * 9 * fout;
        wtrans_kernel<<<(wtot + 255) / 256, 256>>>(Wb, Ws, wt, fin, fout);

        dim3 g(N / 128, fout / 64);
        kan_gemm_kernel<<<g, 256>>>(pn, sp, wt, bbv, conv, N, fin, fout);

        cudaMemsetAsync(bn, 0, 2 * fout * sizeof(float), 0);
        bn_stats_kernel<<<(N + 511) / 512, 256>>>(conv, bn, N, fout, 512);

        float* xout = (l == 0) ? x1 : (l == 1) ? x2 : (float*)d_out;
        int tot = B * fout * (H / 2) * (W / 2);
        bn_pool_kernel<<<(tot + 255) / 256, 256>>>(conv, bn, gam, bet, xout,
                                                   B, fout, H, W);
        xin = xout;
    }
}

// round 3
// speedup vs baseline: 1.2934x; 1.2934x over previous
#include <cuda_runtime.h>
#include <cuda_bf16.h>
#include <math.h>
#include <stdint.h>

// ---------------------------------------------------------------------------
// FastKAN 3-layer conv net — HMMA (mma.sync bf16) tensor-core version.
// tcgen05 is sm_103a-gated and the harness compiles at compute_103, so we use
// the baseline-ISA warp MMA path.
//
// GEMM per layer: C[N,fout] = A_ext[N,K_ext] @ B_ext[K_ext,fout], K_ext=fin*32.
// Per patch feature, 9 basis values (silu + 8 RBF) are bf16 hi/lo split into
// 27 K-slots (+5 zero pad):  slot = 3*t + term,
//   A: term 0,1 -> ah_t ; term 2 -> al_t
//   B: term 0 -> bh_t ; term 1 -> bl_t ; term 2 -> bh_t
// => ah*bh + ah*bl + al*bh ~= a*b  (err ~2^-18).
// A tiles are expanded on the fly in SMEM and read via ldmatrix; B is
// pre-packed in global memory in HMMA fragment order (direct LDG, L1-cached).
// ---------------------------------------------------------------------------

#define MAXF_PN   (131072 * 144)
#define MAXF_CONV (131072 * 64)
#define MAXF_X1   (32 * 64 * 32 * 32)
#define MAXF_X2   (32 * 128 * 16 * 16)
#define MAX_WTB32 (1152 * 16 * 256)     // b32 count = fin*16*fout max = 4,718,592

__device__ float g_pn[MAXF_PN];
__device__ float g_sp[MAXF_PN];
__device__ uint32_t g_wtb[MAX_WTB32];
__device__ float g_conv[MAXF_CONV];
__device__ float g_x1[MAXF_X1];
__device__ float g_x2[MAXF_X2];
__device__ float g_bn[2 * 256];

// ------------------------------ helpers -----------------------------------
__device__ __forceinline__ uint32_t s2u(const void* p) {
    uint32_t a;
    asm("{ .reg .u64 t; cvta.to.shared.u64 t, %1; cvt.u32.u64 %0, t; }"
        : "=r"(a) : "l"(p));
    return a;
}
__device__ __forceinline__ void cp16(uint32_t dst, const void* src) {
    asm volatile("cp.async.cg.shared.global [%0], [%1], 16;" :: "r"(dst), "l"(src));
}
__device__ __forceinline__ void cpwait0() {
    asm volatile("cp.async.commit_group;\n\tcp.async.wait_group 0;" ::: "memory");
}
__device__ __forceinline__ void ldmatrix_x4(uint32_t* r, uint32_t addr) {
    asm volatile("ldmatrix.sync.aligned.m8n8.x4.shared.b16 {%0,%1,%2,%3}, [%4];"
                 : "=r"(r[0]), "=r"(r[1]), "=r"(r[2]), "=r"(r[3]) : "r"(addr));
}
__device__ __forceinline__ void mma16816(float* c, const uint32_t* a,
                                         uint32_t b0, uint32_t b1) {
    asm volatile(
        "mma.sync.aligned.m16n8k16.row.col.f32.bf16.bf16.f32 "
        "{%0,%1,%2,%3}, {%4,%5,%6,%7}, {%8,%9}, {%0,%1,%2,%3};"
        : "+f"(c[0]), "+f"(c[1]), "+f"(c[2]), "+f"(c[3])
        : "r"(a[0]), "r"(a[1]), "r"(a[2]), "r"(a[3]), "r"(b0), "r"(b1));
}

// ---------------------------------------------------------------------------
// 1) patch gather + LayerNorm + SiLU (unchanged; validated in R1)
// ---------------------------------------------------------------------------
__global__ void prep_kernel(const float* __restrict__ x,
                            const float* __restrict__ lnw,
                            const float* __restrict__ lnb,
                            float* __restrict__ pn, float* __restrict__ sp,
                            int C, int H, int W, int fin, int N)
{
    int warp = (blockIdx.x * blockDim.x + threadIdx.x) >> 5;
    int lane = threadIdx.x & 31;
    if (warp >= N) return;
    int w = warp % W;
    int h = (warp / W) % H;
    int b = warp / (W * H);
    const float* xb = x + (size_t)b * C * H * W;

    float s = 0.f, s2 = 0.f;
    for (int f = lane; f < fin; f += 32) {
        int c = f / 9, r = f - c * 9;
        int hh = h + r / 3 - 1, ww = w + (r % 3) - 1;
        float v = 0.f;
        if (hh >= 0 && hh < H && ww >= 0 && ww < W)
            v = xb[(c * H + hh) * W + ww];
        s += v; s2 += v * v;
    }
#pragma unroll
    for (int o = 16; o; o >>= 1) {
        s  += __shfl_xor_sync(0xffffffffu, s,  o);
        s2 += __shfl_xor_sync(0xffffffffu, s2, o);
    }
    float inv  = 1.f / (float)fin;
    float mu   = s * inv;
    float var  = fmaxf(s2 * inv - mu * mu, 0.f);
    float rstd = rsqrtf(var + 1e-5f);

    size_t base = (size_t)warp * fin;
    for (int f = lane; f < fin; f += 32) {
        int c = f / 9, r = f - c * 9;
        int hh = h + r / 3 - 1, ww = w + (r % 3) - 1;
        float v = 0.f;
        if (hh >= 0 && hh < H && ww >= 0 && ww < W)
            v = xb[(c * H + hh) * W + ww];
        pn[base + f] = (v - mu) * rstd * lnw[f] + lnb[f];
        sp[base + f] = v / (1.f + __expf(-v));
    }
}

// ---------------------------------------------------------------------------
// 2) weight prep: pack B directly in HMMA fragment order.
//    b32 idx: ((cs*(fout/8) + tg)*32 + lane)*2 + r
//      cs = global k16 step, tg = global n8 tile.
//    b32 holds bf16 pair for k = cs*16 + (lane&3)*2 + r*8 (+1), n = tg*8+lane/4
// ---------------------------------------------------------------------------
__global__ void wtrans_frag_kernel(const float* __restrict__ Wb,
                                   const float* __restrict__ Ws,
                                   uint32_t* __restrict__ wtb,
                                   int fin, int fout)
{
    int idx = blockIdx.x * blockDim.x + threadIdx.x;
    int nt = fout >> 3;
    int total = fin * 16 * fout;          // b32 elements
    if (idx >= total) return;
    int r  = idx & 1;
    int l  = (idx >> 1) & 31;
    int tg = (idx >> 6) % nt;
    int cs = idx / (64 * nt);
    int n  = tg * 8 + (l >> 2);
    int k0 = cs * 16 + (l & 3) * 2 + r * 8;

    float f2[2];
#pragma unroll
    for (int e = 0; e < 2; e++) {
        int k = k0 + e;
        int i = k >> 5, slot = k & 31;
        float v = 0.f;
        if (slot < 27) {
            int t9 = slot / 3, term = slot % 3;
            float w = (t9 == 0) ? Wb[(size_t)n * fin + i]
                                : Ws[(size_t)n * fin * 8 + i * 8 + (t9 - 1)];
            __nv_bfloat16 h = __float2bfloat16(w);
            v = (term == 1) ? (w - __bfloat162float(h)) : __bfloat162float(h);
        }
        f2[e] = v;
    }
    __nv_bfloat162 p;
    p.x = __float2bfloat16(f2[0]);
    p.y = __float2bfloat16(f2[1]);
    wtb[idx] = *(uint32_t*)&p;
}

// ---------------------------------------------------------------------------
// 3) fused KAN HMMA kernel. CTA: 128 rows x (64*MTILES) cols, 256 threads.
//    Chunk = 2 patch features = 64 expanded K (128B per A row in SMEM).
// ---------------------------------------------------------------------------
template<int MTILES>
__global__ __launch_bounds__(256)
void kan_mma_kernel(const float* __restrict__ pn, const float* __restrict__ sp,
                    const uint32_t* __restrict__ wtb,
                    const float* __restrict__ bb,
                    float* __restrict__ out, int fin, int fout)
{
    constexpr int WARPS_N = MTILES;        // warp cols fixed at 64
    constexpr int NTILE   = 64 * WARPS_N;

    __shared__ __align__(1024) char As[128 * 128];   // 16KB A tile
    __shared__ float pn_s[128 * 12];                 // 48B pitch rows
    __shared__ float sp_s[128 * 12];

    int tid  = threadIdx.x;
    int lane = tid & 31;
    int wid  = tid >> 5;
    int row0 = blockIdx.x * 128;
    int n0   = blockIdx.y * NTILE;
    int warp_n = wid % WARPS_N;
    int warp_m = wid / WARPS_N;
    int wrow = warp_m * (16 * WARPS_N);
    int wcol = warp_n * 64;
    int ntglob = fout >> 3;
    int n0g = (n0 + wcol) >> 3;
    uint32_t Ab = s2u(As);

    float acc[MTILES][8][4];
#pragma unroll
    for (int mt = 0; mt < MTILES; mt++)
#pragma unroll
        for (int t = 0; t < 8; t++)
#pragma unroll
            for (int q = 0; q < 4; q++) acc[mt][t][q] = 0.f;

    int m  = tid & 127;
    int fl = tid >> 7;
    int ngrp = fin >> 3;

    for (int fg = 0; fg < ngrp; fg++) {
        // ---- stage pn/sp: 8 features x 128 rows ----
#pragma unroll
        for (int k2 = 0; k2 < 2; k2++) {
            int id   = tid + 256 * k2;
            int arr  = id >> 8;
            int rr   = (id >> 1) & 127;
            int half = id & 1;
            const float* src = (arr ? sp : pn)
                             + (size_t)(row0 + rr) * fin + fg * 8 + half * 4;
            float* dstp = (arr ? sp_s : pn_s) + rr * 12 + half * 4;
            cp16(s2u(dstp), src);
        }
        cpwait0();
        __syncthreads();

#pragma unroll
        for (int sub = 0; sub < 4; sub++) {
            int chunk = fg * 4 + sub;
            // ---- expand basis for (row m, feature 2*chunk+fl) ----
            {
                float xv = pn_s[m * 12 + sub * 2 + fl];
                float sv = sp_s[m * 12 + sub * 2 + fl];
                float vals[9];
                vals[0] = sv;
#pragma unroll
                for (int j = 0; j < 8; j++) {
                    float g = -2.f + (float)j * (4.f / 7.f);
                    float t = (xv - g) * 1.75f;
                    vals[1 + j] = __expf(-t * t);
                }
                __nv_bfloat16 cv[32];
#pragma unroll
                for (int t9 = 0; t9 < 9; t9++) {
                    __nv_bfloat16 h = __float2bfloat16(vals[t9]);
                    __nv_bfloat16 lo = __float2bfloat16(vals[t9] - __bfloat162float(h));
                    cv[3 * t9]     = h;
                    cv[3 * t9 + 1] = h;
                    cv[3 * t9 + 2] = lo;
                }
#pragma unroll
                for (int z = 27; z < 32; z++) cv[z] = __float2bfloat16(0.f);
                uint32_t wpk[16];
#pragma unroll
                for (int i = 0; i < 16; i++) {
                    __nv_bfloat162 p2;
                    p2.x = cv[2 * i]; p2.y = cv[2 * i + 1];
                    wpk[i] = *(uint32_t*)&p2;
                }
#pragma unroll
                for (int j2 = 0; j2 < 4; j2++) {
                    uint32_t col = (uint32_t)((fl * 4 + j2) ^ (m & 7));
                    uint32_t ad  = Ab + (uint32_t)m * 128 + col * 16;
                    asm volatile("st.shared.v4.b32 [%0], {%1,%2,%3,%4};"
                                 :: "r"(ad), "r"(wpk[4 * j2]), "r"(wpk[4 * j2 + 1]),
                                    "r"(wpk[4 * j2 + 2]), "r"(wpk[4 * j2 + 3]));
                }
            }
            __syncthreads();
            // ---- 4 k16 steps of HMMA ----
#pragma unroll
            for (int s = 0; s < 4; s++) {
                uint32_t af[MTILES][4];
#pragma unroll
                for (int mt = 0; mt < MTILES; mt++) {
                    int j   = lane >> 3, rr2 = lane & 7;
                    int arow = wrow + mt * 16 + (j & 1) * 8 + rr2;
                    int acol = (s * 2 + (j >> 1)) ^ (arow & 7);
                    ldmatrix_x4(af[mt], Ab + (uint32_t)arow * 128 + (uint32_t)acol * 16);
                }
                int cs = chunk * 4 + s;
                const uint2* bp = (const uint2*)wtb
                                + ((size_t)cs * ntglob + n0g) * 32 + lane;
#pragma unroll
                for (int t = 0; t < 8; t++) {
                    uint2 bf = bp[t * 32];
#pragma unroll
                    for (int mt = 0; mt < MTILES; mt++)
                        mma16816(acc[mt][t], af[mt], bf.x, bf.y);
                }
            }
            __syncthreads();
        }
    }

    // ---- epilogue: +bias, store fp32 ----
#pragma unroll
    for (int mt = 0; mt < MTILES; mt++)
#pragma unroll
        for (int t = 0; t < 8; t++) {
            int gcol = n0 + wcol + t * 8 + (lane & 3) * 2;
            float2 bv = *(const float2*)&bb[gcol];
            int r0 = row0 + wrow + mt * 16 + (lane >> 2);
            float2 v0 = { acc[mt][t][0] + bv.x, acc[mt][t][1] + bv.y };
            float2 v1 = { acc[mt][t][2] + bv.x, acc[mt][t][3] + bv.y };
            *(float2*)&out[(size_t)r0 * fout + gcol]       = v0;
            *(float2*)&out[(size_t)(r0 + 8) * fout + gcol] = v1;
        }
}

// ---------------------------------------------------------------------------
// 4) BN batch stats
// ---------------------------------------------------------------------------
__global__ void bn_stats_kernel(const float* __restrict__ conv,
                                float* __restrict__ bn,
                                int N, int fout, int rows_per_block)
{
    __shared__ float r1[256];
    __shared__ float r2[256];
    int t   = threadIdx.x;
    int o   = t % fout;
    int rl  = t / fout;
    int rpb = 256 / fout;
    int n0  = blockIdx.x * rows_per_block;
    int n1  = min(N, n0 + rows_per_block);
    float s = 0.f, s2 = 0.f;
    for (int n = n0 + rl; n < n1; n += rpb) {
        float v = conv[(size_t)n * fout + o];
        s += v; s2 += v * v;
    }
    r1[t] = s; r2[t] = s2;
    __syncthreads();
    for (int off = 128; off >= fout; off >>= 1) {
        if (t < off) { r1[t] += r1[t + off]; r2[t] += r2[t + off]; }
        __syncthreads();
    }
    if (t < fout) {
        atomicAdd(&bn[t],        r1[t]);
        atomicAdd(&bn[fout + t], r2[t]);
    }
}

// ---------------------------------------------------------------------------
// 5) BN apply + ReLU + 2x2 maxpool, output NCHW
// ---------------------------------------------------------------------------
__global__ void bn_pool_kernel(const float* __restrict__ conv,
                               const float* __restrict__ bn,
                               const float* __restrict__ gamma,
                               const float* __restrict__ beta,
                               float* __restrict__ xout,
                               int B, int fout, int H, int W)
{
    int H2 = H >> 1, W2 = W >> 1;
    int idx = blockIdx.x * blockDim.x + threadIdx.x;
    int total = B * fout * H2 * W2;
    if (idx >= total) return;
    int o = idx % fout;
    int r = idx / fout;
    int w2 = r % W2; r /= W2;
    int h2 = r % H2;
    int b  = r / H2;

    float cnt  = (float)(B * H * W);
    float mean = bn[o] / cnt;
    float var  = bn[fout + o] / cnt - mean * mean;
    float sc   = gamma[o] * rsqrtf(var + 1e-5f);
    float sh   = beta[o] - mean * sc;

    int h = h2 * 2, w = w2 * 2;
    size_t base = ((size_t)(b * H + h) * W + w) * fout + o;
    float v00 = conv[base];
    float v01 = conv[base + fout];
    float v10 = conv[base + (size_t)W * fout];
    float v11 = conv[base + (size_t)W * fout + fout];
    float mx = fmaxf(fmaxf(fmaxf(v00 * sc + sh, 0.f), fmaxf(v01 * sc + sh, 0.f)),
                     fmaxf(fmaxf(v10 * sc + sh, 0.f), fmaxf(v11 * sc + sh, 0.f)));
    xout[((size_t)(b * fout + o) * H2 + h2) * W2 + w2] = mx;
}

// ---------------------------------------------------------------------------
extern "C" void kernel_launch(void* const* d_in, const int* in_sizes, int n_in,
                              void* d_out, int out_size)
{
    (void)in_sizes; (void)n_in; (void)out_size;

    float *pn, *sp, *conv, *x1, *x2, *bn;
    uint32_t* wtb;
    cudaGetSymbolAddress((void**)&pn,   g_pn);
    cudaGetSymbolAddress((void**)&sp,   g_sp);
    cudaGetSymbolAddress((void**)&wtb,  g_wtb);
    cudaGetSymbolAddress((void**)&conv, g_conv);
    cudaGetSymbolAddress((void**)&x1,   g_x1);
    cudaGetSymbolAddress((void**)&x2,   g_x2);
    cudaGetSymbolAddress((void**)&bn,   g_bn);

    struct LCfg { int B, C, H, W, fin, fout; };
    const LCfg L[3] = {
        {32,  16, 64, 64,  144,  64},
        {32,  64, 32, 32,  576, 128},
        {32, 128, 16, 16, 1152, 256},
    };

    const float* xin = (const float*)d_in[0];
    for (int l = 0; l < 3; l++) {
        const float* lnw = (const float*)d_in[1 + 7 * l + 0];
        const float* lnb = (const float*)d_in[1 + 7 * l + 1];
        const float* Wb  = (const float*)d_in[1 + 7 * l + 2];
        const float* bbv = (const float*)d_in[1 + 7 * l + 3];
        const float* Ws  = (const float*)d_in[1 + 7 * l + 4];
        const float* gam = (const float*)d_in[1 + 7 * l + 5];
        const float* bet = (const float*)d_in[1 + 7 * l + 6];

        int B = L[l].B, C = L[l].C, H = L[l].H, W = L[l].W;
        int fin = L[l].fin, fout = L[l].fout;
        int N = B * H * W;

        prep_kernel<<<(N + 7) / 8, 256>>>(xin, lnw, lnb, pn, sp, C, H, W, fin, N);

        int wtot = fin * 16 * fout;
        wtrans_frag_kernel<<<(wtot + 255) / 256, 256>>>(Wb, Ws, wtb, fin, fout);

        if (fout == 64) {
            dim3 g(N / 128, 1);
            kan_mma_kernel<1><<<g, 256>>>(pn, sp, wtb, bbv, conv, fin, fout);
        } else {
            dim3 g(N / 128, fout / 128);
            kan_mma_kernel<2><<<g, 256>>>(pn, sp, wtb, bbv, conv, fin, fout);
        }

        cudaMemsetAsync(bn, 0, 2 * fout * sizeof(float), 0);
        bn_stats_kernel<<<(N + 511) / 512, 256>>>(conv, bn, N, fout, 512);

        float* xout = (l == 0) ? x1 : (l == 1) ? x2 : (float*)d_out;
        int tot = B * fout * (H / 2) * (W / 2);
        bn_pool_kernel<<<(tot + 255) / 256, 256>>>(conv, bn, gam, bet, xout,
                                                   B, fout, H, W);
        xin = xout;
    }
}

// round 4
// speedup vs baseline: 1.7211x; 1.3307x over previous
#include <cuda_runtime.h>
#include <cuda_bf16.h>
#include <math.h>
#include <stdint.h>

// ---------------------------------------------------------------------------
// FastKAN 3-layer conv net — HMMA (mma.sync bf16) with software pipelining.
// A_ext expanded on the fly (silu + 8 RBF, bf16 hi/lo 3-term split, 27+5 slots
// per feature); B pre-packed in HMMA fragment order in global.
// R4: double-buffered A tile (1 sync/chunk, expansion overlaps MMA),
//     double-buffered pn/sp staging, truncation split + byte_perm packing,
//     B fragment register lookahead.
// ---------------------------------------------------------------------------

#define MAXF_PN   (131072 * 144)
#define MAXF_CONV (131072 * 64)
#define MAXF_X1   (32 * 64 * 32 * 32)
#define MAXF_X2   (32 * 128 * 16 * 16)
#define MAX_WTB32 (1152 * 16 * 256)

__device__ float g_pn[MAXF_PN];
__device__ float g_sp[MAXF_PN];
__device__ uint32_t g_wtb[MAX_WTB32];
__device__ float g_conv[MAXF_CONV];
__device__ float g_x1[MAXF_X1];
__device__ float g_x2[MAXF_X2];
__device__ float g_bn[2 * 256];

// ------------------------------ helpers -----------------------------------
__device__ __forceinline__ uint32_t s2u(const void* p) {
    uint32_t a;
    asm("{ .reg .u64 t; cvta.to.shared.u64 t, %1; cvt.u32.u64 %0, t; }"
        : "=r"(a) : "l"(p));
    return a;
}
__device__ __forceinline__ void cp16(uint32_t dst, const void* src) {
    asm volatile("cp.async.cg.shared.global [%0], [%1], 16;" :: "r"(dst), "l"(src));
}
__device__ __forceinline__ void cp_commit() {
    asm volatile("cp.async.commit_group;" ::: "memory");
}
template<int N>
__device__ __forceinline__ void cp_wait() {
    asm volatile("cp.async.wait_group %0;" :: "n"(N) : "memory");
}
__device__ __forceinline__ void ldmatrix_x4(uint32_t* r, uint32_t addr) {
    asm volatile("ldmatrix.sync.aligned.m8n8.x4.shared.b16 {%0,%1,%2,%3}, [%4];"
                 : "=r"(r[0]), "=r"(r[1]), "=r"(r[2]), "=r"(r[3]) : "r"(addr));
}
__device__ __forceinline__ void mma16816(float* c, const uint32_t* a,
                                         uint32_t b0, uint32_t b1) {
    asm volatile(
        "mma.sync.aligned.m16n8k16.row.col.f32.bf16.bf16.f32 "
        "{%0,%1,%2,%3}, {%4,%5,%6,%7}, {%8,%9}, {%0,%1,%2,%3};"
        : "+f"(c[0]), "+f"(c[1]), "+f"(c[2]), "+f"(c[3])
        : "r"(a[0]), "r"(a[1]), "r"(a[2]), "r"(a[3]), "r"(b0), "r"(b1));
}

// ---------------------------------------------------------------------------
// 1) patch gather + LayerNorm + SiLU
// ---------------------------------------------------------------------------
__global__ void prep_kernel(const float* __restrict__ x,
                            const float* __restrict__ lnw,
                            const float* __restrict__ lnb,
                            float* __restrict__ pn, float* __restrict__ sp,
                            int C, int H, int W, int fin, int N)
{
    int warp = (blockIdx.x * blockDim.x + threadIdx.x) >> 5;
    int lane = threadIdx.x & 31;
    if (warp >= N) return;
    int w = warp % W;
    int h = (warp / W) % H;
    int b = warp / (W * H);
    const float* xb = x + (size_t)b * C * H * W;

    float s = 0.f, s2 = 0.f;
    for (int f = lane; f < fin; f += 32) {
        int c = f / 9, r = f - c * 9;
        int hh = h + r / 3 - 1, ww = w + (r % 3) - 1;
        float v = 0.f;
        if (hh >= 0 && hh < H && ww >= 0 && ww < W)
            v = xb[(c * H + hh) * W + ww];
        s += v; s2 += v * v;
    }
#pragma unroll
    for (int o = 16; o; o >>= 1) {
        s  += __shfl_xor_sync(0xffffffffu, s,  o);
        s2 += __shfl_xor_sync(0xffffffffu, s2, o);
    }
    float inv  = 1.f / (float)fin;
    float mu   = s * inv;
    float var  = fmaxf(s2 * inv - mu * mu, 0.f);
    float rstd = rsqrtf(var + 1e-5f);

    size_t base = (size_t)warp * fin;
    for (int f = lane; f < fin; f += 32) {
        int c = f / 9, r = f - c * 9;
        int hh = h + r / 3 - 1, ww = w + (r % 3) - 1;
        float v = 0.f;
        if (hh >= 0 && hh < H && ww >= 0 && ww < W)
            v = xb[(c * H + hh) * W + ww];
        pn[base + f] = (v - mu) * rstd * lnw[f] + lnb[f];
        sp[base + f] = v / (1.f + __expf(-v));
    }
}

// ---------------------------------------------------------------------------
// 2) weight prep: pack B in HMMA fragment order (unchanged from R3).
// ---------------------------------------------------------------------------
__global__ void wtrans_frag_kernel(const float* __restrict__ Wb,
                                   const float* __restrict__ Ws,
                                   uint32_t* __restrict__ wtb,
                                   int fin, int fout)
{
    int idx = blockIdx.x * blockDim.x + threadIdx.x;
    int nt = fout >> 3;
    int total = fin * 16 * fout;
    if (idx >= total) return;
    int r  = idx & 1;
    int l  = (idx >> 1) & 31;
    int tg = (idx >> 6) % nt;
    int cs = idx / (64 * nt);
    int n  = tg * 8 + (l >> 2);
    int k0 = cs * 16 + (l & 3) * 2 + r * 8;

    float f2[2];
#pragma unroll
    for (int e = 0; e < 2; e++) {
        int k = k0 + e;
        int i = k >> 5, slot = k & 31;
        float v = 0.f;
        if (slot < 27) {
            int t9 = slot / 3, term = slot % 3;
            float w = (t9 == 0) ? Wb[(size_t)n * fin + i]
                                : Ws[(size_t)n * fin * 8 + i * 8 + (t9 - 1)];
            __nv_bfloat16 h = __float2bfloat16(w);
            v = (term == 1) ? (w - __bfloat162float(h)) : __bfloat162float(h);
        }
        f2[e] = v;
    }
    __nv_bfloat162 p;
    p.x = __float2bfloat16(f2[0]);
    p.y = __float2bfloat16(f2[1]);
    wtb[idx] = *(uint32_t*)&p;
}

// ---------------------------------------------------------------------------
// 3) fused KAN HMMA kernel, software-pipelined.
//    CTA: 128 rows x (64*MTILES) cols, 256 threads.
//    Chunk = 2 features = 64 expanded K slots; A tile double-buffered.
// ---------------------------------------------------------------------------
template<int MTILES>
__global__ __launch_bounds__(256, 2)
void kan_mma_kernel(const float* __restrict__ pn, const float* __restrict__ sp,
                    const uint32_t* __restrict__ wtb,
                    const float* __restrict__ bb,
                    float* __restrict__ out, int fin, int fout)
{
    constexpr int WARPS_N = MTILES;
    constexpr int NTILE   = 64 * WARPS_N;

    extern __shared__ char smem[];
    uint32_t sb  = s2u(smem);
    uint32_t Ab0 = (sb + 1023) & ~1023u;       // two 16KB A buffers
    uint32_t pnb = Ab0 + 32768;                // two 4KB pn buffers
    uint32_t spb = pnb + 8192;                 // two 4KB sp buffers
    const char* smc = smem + (Ab0 - sb);       // generic-space view of Ab0

    int tid  = threadIdx.x;
    int lane = tid & 31;
    int wid  = tid >> 5;
    int row0 = blockIdx.x * 128;
    int n0   = blockIdx.y * NTILE;
    int warp_n = wid % WARPS_N;
    int warp_m = wid / WARPS_N;
    int wrow = warp_m * (16 * WARPS_N);
    int wcol = warp_n * 64;
    int ntglob = fout >> 3;
    int n0g = (n0 + wcol) >> 3;

    float acc[MTILES][8][4];
#pragma unroll
    for (int mt = 0; mt < MTILES; mt++)
#pragma unroll
        for (int t = 0; t < 8; t++)
#pragma unroll
            for (int q = 0; q < 4; q++) acc[mt][t][q] = 0.f;

    int m  = tid & 127;
    int fl = tid >> 7;
    int ngrp = fin >> 3;
    int C = ngrp * 4;

    // ---- pn/sp group staging (double-buffered) ----
    // thread stages: rr = tid>>1, half = tid&1, both arrays.
    int rr   = tid >> 1;
    int half = tid & 1;
    const float* pn_src0 = pn + (size_t)(row0 + rr) * fin + half * 4;
    const float* sp_src0 = sp + (size_t)(row0 + rr) * fin + half * 4;
    uint32_t pn_dst = pnb + (uint32_t)rr * 32 + (uint32_t)half * 16;
    uint32_t sp_dst = spb + (uint32_t)rr * 32 + (uint32_t)half * 16;

    // prologue: stage group 0 into buffer 0
    cp16(pn_dst, pn_src0);
    cp16(sp_dst, sp_src0);
    cp_commit();

    for (int fg = 0; fg < ngrp; fg++) {
        if (fg + 1 < ngrp) {
            uint32_t boff = (uint32_t)((fg + 1) & 1) << 12;
            cp16(pn_dst + boff, pn_src0 + (fg + 1) * 8);
            cp16(sp_dst + boff, sp_src0 + (fg + 1) * 8);
            cp_commit();
            cp_wait<1>();
        } else {
            cp_wait<0>();
        }
        __syncthreads();   // pn/sp group fg visible to all

        const float* pnB = (const float*)(smc + 32768 + ((fg & 1) << 12));
        const float* spB = (const float*)(smc + 40960 + ((fg & 1) << 12));

#pragma unroll
        for (int sub = 0; sub < 4; sub++) {
            int c = fg * 4 + sub;
            // ---------- expand chunk c into A buf[c&1] ----------
            {
                int feat = sub * 2 + fl;
                float xv = pnB[m * 8 + feat];
                float sv = spB[m * 8 + feat];
                float vals[9];
                vals[0] = sv;
#pragma unroll
                for (int j = 0; j < 8; j++) {
                    float g = -2.f + (float)j * (4.f / 7.f);
                    float t = (xv - g) * 1.75f;
                    vals[1 + j] = __expf(-t * t);
                }
                uint32_t vb[9], lb[9];
#pragma unroll
                for (int t9 = 0; t9 < 9; t9++) {
                    uint32_t b = __float_as_uint(vals[t9]);
                    vb[t9] = b;
                    float hf = __uint_as_float(b & 0xFFFF0000u);
                    lb[t9] = (uint32_t)__bfloat16_as_ushort(
                                 __float2bfloat16(vals[t9] - hf));
                }
                uint32_t wpk[16];
#pragma unroll
                for (int p = 0; p < 4; p++) {
                    wpk[3 * p + 0] = __byte_perm(vb[2 * p],     vb[2 * p],     0x3232);
                    wpk[3 * p + 1] = __byte_perm(lb[2 * p],     vb[2 * p + 1], 0x7610);
                    wpk[3 * p + 2] = __byte_perm(vb[2 * p + 1], lb[2 * p + 1], 0x5432);
                }
                wpk[12] = __byte_perm(vb[8], vb[8], 0x3232);
                wpk[13] = lb[8];
                wpk[14] = 0u;
                wpk[15] = 0u;

                uint32_t Abase = Ab0 + ((uint32_t)(c & 1) << 14);
#pragma unroll
                for (int j2 = 0; j2 < 4; j2++) {
                    uint32_t col = (uint32_t)((fl * 4 + j2) ^ (m & 7));
                    uint32_t ad  = Abase + (uint32_t)m * 128 + col * 16;
                    asm volatile("st.shared.v4.b32 [%0], {%1,%2,%3,%4};"
                                 :: "r"(ad), "r"(wpk[4 * j2]), "r"(wpk[4 * j2 + 1]),
                                    "r"(wpk[4 * j2 + 2]), "r"(wpk[4 * j2 + 3]));
                }
            }
            // ---------- MMA chunk c-1 from A buf[(c-1)&1] ----------
            if (c > 0) {
                int cm = c - 1;
                uint32_t Abase = Ab0 + ((uint32_t)(cm & 1) << 14);
                int j = lane >> 3, rr2 = lane & 7;
                // prime B for step 0
                uint2 bf[2][8];
                {
                    const uint2* bp = (const uint2*)wtb
                                    + ((size_t)(cm * 4) * ntglob + n0g) * 32 + lane;
#pragma unroll
                    for (int t = 0; t < 8; t++) bf[0][t] = __ldg(bp + t * 32);
                }
#pragma unroll
                for (int s = 0; s < 4; s++) {
                    if (s < 3) {
                        const uint2* bp = (const uint2*)wtb
                                        + ((size_t)(cm * 4 + s + 1) * ntglob + n0g) * 32 + lane;
#pragma unroll
                        for (int t = 0; t < 8; t++) bf[(s + 1) & 1][t] = __ldg(bp + t * 32);
                    }
                    uint32_t af[MTILES][4];
#pragma unroll
                    for (int mt = 0; mt < MTILES; mt++) {
                        int arow = wrow + mt * 16 + (j & 1) * 8 + rr2;
                        int acol = (s * 2 + (j >> 1)) ^ (arow & 7);
                        ldmatrix_x4(af[mt], Abase + (uint32_t)arow * 128
                                           + (uint32_t)acol * 16);
                    }
#pragma unroll
                    for (int t = 0; t < 8; t++)
#pragma unroll
                        for (int mt = 0; mt < MTILES; mt++)
                            mma16816(acc[mt][t], af[mt], bf[s & 1][t].x, bf[s & 1][t].y);
                }
            }
            __syncthreads();
        }
    }

    // ---------- final chunk MMA ----------
    {
        int cm = C - 1;
        uint32_t Abase = Ab0 + ((uint32_t)(cm & 1) << 14);
        int j = lane >> 3, rr2 = lane & 7;
#pragma unroll
        for (int s = 0; s < 4; s++) {
            uint32_t af[MTILES][4];
#pragma unroll
            for (int mt = 0; mt < MTILES; mt++) {
                int arow = wrow + mt * 16 + (j & 1) * 8 + rr2;
                int acol = (s * 2 + (j >> 1)) ^ (arow & 7);
                ldmatrix_x4(af[mt], Abase + (uint32_t)arow * 128
                                   + (uint32_t)acol * 16);
            }
            const uint2* bp = (const uint2*)wtb
                            + ((size_t)(cm * 4 + s) * ntglob + n0g) * 32 + lane;
            uint2 bf[8];
#pragma unroll
            for (int t = 0; t < 8; t++) bf[t] = __ldg(bp + t * 32);
#pragma unroll
            for (int t = 0; t < 8; t++)
#pragma unroll
                for (int mt = 0; mt < MTILES; mt++)
                    mma16816(acc[mt][t], af[mt], bf[t].x, bf[t].y);
        }
    }

    // ---------- epilogue: +bias, store fp32 ----------
#pragma unroll
    for (int mt = 0; mt < MTILES; mt++)
#pragma unroll
        for (int t = 0; t < 8; t++) {
            int gcol = n0 + wcol + t * 8 + (lane & 3) * 2;
            float2 bv = *(const float2*)&bb[gcol];
            int r0 = row0 + wrow + mt * 16 + (lane >> 2);
            float2 v0 = { acc[mt][t][0] + bv.x, acc[mt][t][1] + bv.y };
            float2 v1 = { acc[mt][t][2] + bv.x, acc[mt][t][3] + bv.y };
            *(float2*)&out[(size_t)r0 * fout + gcol]       = v0;
            *(float2*)&out[(size_t)(r0 + 8) * fout + gcol] = v1;
        }
}

// ---------------------------------------------------------------------------
// 4) BN batch stats
// ---------------------------------------------------------------------------
__global__ void bn_stats_kernel(const float* __restrict__ conv,
                                float* __restrict__ bn,
                                int N, int fout, int rows_per_block)
{
    __shared__ float r1[256];
    __shared__ float r2[256];
    int t   = threadIdx.x;
    int o   = t % fout;
    int rl  = t / fout;
    int rpb = 256 / fout;
    int n0  = blockIdx.x * rows_per_block;
    int n1  = min(N, n0 + rows_per_block);
    float s = 0.f, s2 = 0.f;
    for (int n = n0 + rl; n < n1; n += rpb) {
        float v = conv[(size_t)n * fout + o];
        s += v; s2 += v * v;
    }
    r1[t] = s; r2[t] = s2;
    __syncthreads();
    for (int off = 128; off >= fout; off >>= 1) {
        if (t < off) { r1[t] += r1[t + off]; r2[t] += r2[t + off]; }
        __syncthreads();
    }
    if (t < fout) {
        atomicAdd(&bn[t],        r1[t]);
        atomicAdd(&bn[fout + t], r2[t]);
    }
}

// ---------------------------------------------------------------------------
// 5) BN apply + ReLU + 2x2 maxpool, output NCHW
// ---------------------------------------------------------------------------
__global__ void bn_pool_kernel(const float* __restrict__ conv,
                               const float* __restrict__ bn,
                               const float* __restrict__ gamma,
                               const float* __restrict__ beta,
                               float* __restrict__ xout,
                               int B, int fout, int H, int W)
{
    int H2 = H >> 1, W2 = W >> 1;
    int idx = blockIdx.x * blockDim.x + threadIdx.x;
    int total = B * fout * H2 * W2;
    if (idx >= total) return;
    int o = idx % fout;
    int r = idx / fout;
    int w2 = r % W2; r /= W2;
    int h2 = r % H2;
    int b  = r / H2;

    float cnt  = (float)(B * H * W);
    float mean = bn[o] / cnt;
    float var  = bn[fout + o] / cnt - mean * mean;
    float sc   = gamma[o] * rsqrtf(var + 1e-5f);
    float sh   = beta[o] - mean * sc;

    int h = h2 * 2, w = w2 * 2;
    size_t base = ((size_t)(b * H + h) * W + w) * fout + o;
    float v00 = conv[base];
    float v01 = conv[base + fout];
    float v10 = conv[base + (size_t)W * fout];
    float v11 = conv[base + (size_t)W * fout + fout];
    float mx = fmaxf(fmaxf(fmaxf(v00 * sc + sh, 0.f), fmaxf(v01 * sc + sh, 0.f)),
                     fmaxf(fmaxf(v10 * sc + sh, 0.f), fmaxf(v11 * sc + sh, 0.f)));
    xout[((size_t)(b * fout + o) * H2 + h2) * W2 + w2] = mx;
}

// ---------------------------------------------------------------------------
extern "C" void kernel_launch(void* const* d_in, const int* in_sizes, int n_in,
                              void* d_out, int out_size)
{
    (void)in_sizes; (void)n_in; (void)out_size;

    float *pn, *sp, *conv, *x1, *x2, *bn;
    uint32_t* wtb;
    cudaGetSymbolAddress((void**)&pn,   g_pn);
    cudaGetSymbolAddress((void**)&sp,   g_sp);
    cudaGetSymbolAddress((void**)&wtb,  g_wtb);
    cudaGetSymbolAddress((void**)&conv, g_conv);
    cudaGetSymbolAddress((void**)&x1,   g_x1);
    cudaGetSymbolAddress((void**)&x2,   g_x2);
    cudaGetSymbolAddress((void**)&bn,   g_bn);

    const int SMEM = 1024 + 32768 + 8192 + 8192;   // 50176
    cudaFuncSetAttribute(kan_mma_kernel<1>,
                         cudaFuncAttributeMaxDynamicSharedMemorySize, SMEM);
    cudaFuncSetAttribute(kan_mma_kernel<2>,
                         cudaFuncAttributeMaxDynamicSharedMemorySize, SMEM);

    struct LCfg { int B, C, H, W, fin, fout; };
    const LCfg L[3] = {
        {32,  16, 64, 64,  144,  64},
        {32,  64, 32, 32,  576, 128},
        {32, 128, 16, 16, 1152, 256},
    };

    const float* xin = (const float*)d_in[0];
    for (int l = 0; l < 3; l++) {
        const float* lnw = (const float*)d_in[1 + 7 * l + 0];
        const float* lnb = (const float*)d_in[1 + 7 * l + 1];
        const float* Wb  = (const float*)d_in[1 + 7 * l + 2];
        const float* bbv = (const float*)d_in[1 + 7 * l + 3];
        const float* Ws  = (const float*)d_in[1 + 7 * l + 4];
        const float* gam = (const float*)d_in[1 + 7 * l + 5];
        const float* bet = (const float*)d_in[1 + 7 * l + 6];

        int B = L[l].B, C = L[l].C, H = L[l].H, W = L[l].W;
        int fin = L[l].fin, fout = L[l].fout;
        int N = B * H * W;

        prep_kernel<<<(N + 7) / 8, 256>>>(xin, lnw, lnb, pn, sp, C, H, W, fin, N);

        int wtot = fin * 16 * fout;
        wtrans_frag_kernel<<<(wtot + 255) / 256, 256>>>(Wb, Ws, wtb, fin, fout);

        if (fout == 64) {
            dim3 g(N / 128, 1);
            kan_mma_kernel<1><<<g, 256, SMEM>>>(pn, sp, wtb, bbv, conv, fin, fout);
        } else {
            dim3 g(N / 128, fout / 128);
            kan_mma_kernel<2><<<g, 256, SMEM>>>(pn, sp, wtb, bbv, conv, fin, fout);
        }

        cudaMemsetAsync(bn, 0, 2 * fout * sizeof(float), 0);
        bn_stats_kernel<<<(N + 511) / 512, 256>>>(conv, bn, N, fout, 512);

        float* xout = (l == 0) ? x1 : (l == 1) ? x2 : (float*)d_out;
        int tot = B * fout * (H / 2) * (W / 2);
        bn_pool_kernel<<<(tot + 255) / 256, 256>>>(conv, bn, gam, bet, xout,
                                                   B, fout, H, W);
        xin = xout;
    }
}

// round 5
// speedup vs baseline: 1.7546x; 1.0195x over previous
#include <cuda_runtime.h>
#include <cuda_bf16.h>
#include <math.h>
#include <stdint.h>

// ---------------------------------------------------------------------------
// FastKAN 3-layer conv net — HMMA (mma.sync bf16), software-pipelined.
// R5: RBF expansion via ratio chain (3 expf instead of 8 per feature):
//   u = 1.75x+3.5, e_j = exp(-(u-j)^2); e_{j+1} = e_j * exp(2(u-j)-1),
//   ratio decays by q = exp(-2) per step; chain from fixed center j=4.
// ---------------------------------------------------------------------------

#define MAXF_PN   (131072 * 144)
#define MAXF_CONV (131072 * 64)
#define MAXF_X1   (32 * 64 * 32 * 32)
#define MAXF_X2   (32 * 128 * 16 * 16)
#define MAX_WTB32 (1152 * 16 * 256)

__device__ float g_pn[MAXF_PN];
__device__ float g_sp[MAXF_PN];
__device__ uint32_t g_wtb[MAX_WTB32];
__device__ float g_conv[MAXF_CONV];
__device__ float g_x1[MAXF_X1];
__device__ float g_x2[MAXF_X2];
__device__ float g_bn[2 * 256];

// ------------------------------ helpers -----------------------------------
__device__ __forceinline__ uint32_t s2u(const void* p) {
    uint32_t a;
    asm("{ .reg .u64 t; cvta.to.shared.u64 t, %1; cvt.u32.u64 %0, t; }"
        : "=r"(a) : "l"(p));
    return a;
}
__device__ __forceinline__ void cp16(uint32_t dst, const void* src) {
    asm volatile("cp.async.cg.shared.global [%0], [%1], 16;" :: "r"(dst), "l"(src));
}
__device__ __forceinline__ void cp_commit() {
    asm volatile("cp.async.commit_group;" ::: "memory");
}
template<int N>
__device__ __forceinline__ void cp_wait() {
    asm volatile("cp.async.wait_group %0;" :: "n"(N) : "memory");
}
__device__ __forceinline__ void ldmatrix_x4(uint32_t* r, uint32_t addr) {
    asm volatile("ldmatrix.sync.aligned.m8n8.x4.shared.b16 {%0,%1,%2,%3}, [%4];"
                 : "=r"(r[0]), "=r"(r[1]), "=r"(r[2]), "=r"(r[3]) : "r"(addr));
}
__device__ __forceinline__ void mma16816(float* c, const uint32_t* a,
                                         uint32_t b0, uint32_t b1) {
    asm volatile(
        "mma.sync.aligned.m16n8k16.row.col.f32.bf16.bf16.f32 "
        "{%0,%1,%2,%3}, {%4,%5,%6,%7}, {%8,%9}, {%0,%1,%2,%3};"
        : "+f"(c[0]), "+f"(c[1]), "+f"(c[2]), "+f"(c[3])
        : "r"(a[0]), "r"(a[1]), "r"(a[2]), "r"(a[3]), "r"(b0), "r"(b1));
}

// ---------------------------------------------------------------------------
// 1) patch gather + LayerNorm + SiLU
// ---------------------------------------------------------------------------
__global__ void prep_kernel(const float* __restrict__ x,
                            const float* __restrict__ lnw,
                            const float* __restrict__ lnb,
                            float* __restrict__ pn, float* __restrict__ sp,
                            int C, int H, int W, int fin, int N)
{
    int warp = (blockIdx.x * blockDim.x + threadIdx.x) >> 5;
    int lane = threadIdx.x & 31;
    if (warp >= N) return;
    int w = warp % W;
    int h = (warp / W) % H;
    int b = warp / (W * H);
    const float* xb = x + (size_t)b * C * H * W;

    float s = 0.f, s2 = 0.f;
    for (int f = lane; f < fin; f += 32) {
        int c = f / 9, r = f - c * 9;
        int hh = h + r / 3 - 1, ww = w + (r % 3) - 1;
        float v = 0.f;
        if (hh >= 0 && hh < H && ww >= 0 && ww < W)
            v = xb[(c * H + hh) * W + ww];
        s += v; s2 += v * v;
    }
#pragma unroll
    for (int o = 16; o; o >>= 1) {
        s  += __shfl_xor_sync(0xffffffffu, s,  o);
        s2 += __shfl_xor_sync(0xffffffffu, s2, o);
    }
    float inv  = 1.f / (float)fin;
    float mu   = s * inv;
    float var  = fmaxf(s2 * inv - mu * mu, 0.f);
    float rstd = rsqrtf(var + 1e-5f);

    size_t base = (size_t)warp * fin;
    for (int f = lane; f < fin; f += 32) {
        int c = f / 9, r = f - c * 9;
        int hh = h + r / 3 - 1, ww = w + (r % 3) - 1;
        float v = 0.f;
        if (hh >= 0 && hh < H && ww >= 0 && ww < W)
            v = xb[(c * H + hh) * W + ww];
        pn[base + f] = (v - mu) * rstd * lnw[f] + lnb[f];
        sp[base + f] = v / (1.f + __expf(-v));
    }
}

// ---------------------------------------------------------------------------
// 2) weight prep: pack B in HMMA fragment order.
// ---------------------------------------------------------------------------
__global__ void wtrans_frag_kernel(const float* __restrict__ Wb,
                                   const float* __restrict__ Ws,
                                   uint32_t* __restrict__ wtb,
                                   int fin, int fout)
{
    int idx = blockIdx.x * blockDim.x + threadIdx.x;
    int nt = fout >> 3;
    int total = fin * 16 * fout;
    if (idx >= total) return;
    int r  = idx & 1;
    int l  = (idx >> 1) & 31;
    int tg = (idx >> 6) % nt;
    int cs = idx / (64 * nt);
    int n  = tg * 8 + (l >> 2);
    int k0 = cs * 16 + (l & 3) * 2 + r * 8;

    float f2[2];
#pragma unroll
    for (int e = 0; e < 2; e++) {
        int k = k0 + e;
        int i = k >> 5, slot = k & 31;
        float v = 0.f;
        if (slot < 27) {
            int t9 = slot / 3, term = slot % 3;
            float w = (t9 == 0) ? Wb[(size_t)n * fin + i]
                                : Ws[(size_t)n * fin * 8 + i * 8 + (t9 - 1)];
            __nv_bfloat16 h = __float2bfloat16(w);
            v = (term == 1) ? (w - __bfloat162float(h)) : __bfloat162float(h);
        }
        f2[e] = v;
    }
    __nv_bfloat162 p;
    p.x = __float2bfloat16(f2[0]);
    p.y = __float2bfloat16(f2[1]);
    wtb[idx] = *(uint32_t*)&p;
}

// ---------------------------------------------------------------------------
// 3) fused KAN HMMA kernel, software-pipelined, ratio-chain RBF expansion.
// ---------------------------------------------------------------------------
template<int MTILES>
__global__ __launch_bounds__(256, 2)
void kan_mma_kernel(const float* __restrict__ pn, const float* __restrict__ sp,
                    const uint32_t* __restrict__ wtb,
                    const float* __restrict__ bb,
                    float* __restrict__ out, int fin, int fout)
{
    constexpr int WARPS_N = MTILES;
    constexpr int NTILE   = 64 * WARPS_N;

    extern __shared__ char smem[];
    uint32_t sb  = s2u(smem);
    uint32_t Ab0 = (sb + 1023) & ~1023u;
    uint32_t pnb = Ab0 + 32768;
    uint32_t spb = pnb + 8192;
    const char* smc = smem + (Ab0 - sb);

    int tid  = threadIdx.x;
    int lane = tid & 31;
    int wid  = tid >> 5;
    int row0 = blockIdx.x * 128;
    int n0   = blockIdx.y * NTILE;
    int warp_n = wid % WARPS_N;
    int warp_m = wid / WARPS_N;
    int wrow = warp_m * (16 * WARPS_N);
    int wcol = warp_n * 64;
    int ntglob = fout >> 3;
    int n0g = (n0 + wcol) >> 3;

    float acc[MTILES][8][4];
#pragma unroll
    for (int mt = 0; mt < MTILES; mt++)
#pragma unroll
        for (int t = 0; t < 8; t++)
#pragma unroll
            for (int q = 0; q < 4; q++) acc[mt][t][q] = 0.f;

    int m  = tid & 127;
    int fl = tid >> 7;
    int ngrp = fin >> 3;
    int C = ngrp * 4;

    int rr   = tid >> 1;
    int half = tid & 1;
    const float* pn_src0 = pn + (size_t)(row0 + rr) * fin + half * 4;
    const float* sp_src0 = sp + (size_t)(row0 + rr) * fin + half * 4;
    uint32_t pn_dst = pnb + (uint32_t)rr * 32 + (uint32_t)half * 16;
    uint32_t sp_dst = spb + (uint32_t)rr * 32 + (uint32_t)half * 16;

    cp16(pn_dst, pn_src0);
    cp16(sp_dst, sp_src0);
    cp_commit();

    for (int fg = 0; fg < ngrp; fg++) {
        if (fg + 1 < ngrp) {
            uint32_t boff = (uint32_t)((fg + 1) & 1) << 12;
            cp16(pn_dst + boff, pn_src0 + (fg + 1) * 8);
            cp16(sp_dst + boff, sp_src0 + (fg + 1) * 8);
            cp_commit();
            cp_wait<1>();
        } else {
            cp_wait<0>();
        }
        __syncthreads();

        const float* pnB = (const float*)(smc + 32768 + ((fg & 1) << 12));
        const float* spB = (const float*)(smc + 40960 + ((fg & 1) << 12));

#pragma unroll
        for (int sub = 0; sub < 4; sub++) {
            int c = fg * 4 + sub;
            // ---------- expand chunk c into A buf[c&1] (ratio chain) ----------
            {
                int feat = sub * 2 + fl;
                float xv = pnB[m * 8 + feat];
                float sv = spB[m * 8 + feat];

                // e_j = exp(-(u-j)^2), u = 1.75x+3.5; chain from center j=4.
                const float q = 0.13533528323661270f;   // exp(-2)
                float u  = fmaf(xv, 1.75f, 3.5f);
                float d  = u - 4.0f;
                float e4 = __expf(-d * d);
                float R  = __expf(fmaf( 2.f, d, -1.f));
                float S  = __expf(fmaf(-2.f, d, -1.f));
                float e5 = e4 * R;  R *= q;
                float e6 = e5 * R;  R *= q;
                float e7 = e6 * R;
                float e3 = e4 * S;  S *= q;
                float e2 = e3 * S;  S *= q;
                float e1 = e2 * S;  S *= q;
                float e0 = e1 * S;

                float vals[9] = { sv, e0, e1, e2, e3, e4, e5, e6, e7 };

                uint32_t vb[9], lb[9];
#pragma unroll
                for (int t9 = 0; t9 < 9; t9++) {
                    uint32_t b = __float_as_uint(vals[t9]);
                    vb[t9] = b;
                    float hf = __uint_as_float(b & 0xFFFF0000u);
                    lb[t9] = (uint32_t)__bfloat16_as_ushort(
                                 __float2bfloat16(vals[t9] - hf));
                }
                uint32_t wpk[16];
#pragma unroll
                for (int p = 0; p < 4; p++) {
                    wpk[3 * p + 0] = __byte_perm(vb[2 * p],     vb[2 * p],     0x3232);
                    wpk[3 * p + 1] = __byte_perm(lb[2 * p],     vb[2 * p + 1], 0x7610);
                    wpk[3 * p + 2] = __byte_perm(vb[2 * p + 1], lb[2 * p + 1], 0x5432);
                }
                wpk[12] = __byte_perm(vb[8], vb[8], 0x3232);
                wpk[13] = lb[8];
                wpk[14] = 0u;
                wpk[15] = 0u;

                uint32_t Abase = Ab0 + ((uint32_t)(c & 1) << 14);
#pragma unroll
                for (int j2 = 0; j2 < 4; j2++) {
                    uint32_t col = (uint32_t)((fl * 4 + j2) ^ (m & 7));
                    uint32_t ad  = Abase + (uint32_t)m * 128 + col * 16;
                    asm volatile("st.shared.v4.b32 [%0], {%1,%2,%3,%4};"
                                 :: "r"(ad), "r"(wpk[4 * j2]), "r"(wpk[4 * j2 + 1]),
                                    "r"(wpk[4 * j2 + 2]), "r"(wpk[4 * j2 + 3]));
                }
            }
            // ---------- MMA chunk c-1 ----------
            if (c > 0) {
                int cm = c - 1;
                uint32_t Abase = Ab0 + ((uint32_t)(cm & 1) << 14);
                int j = lane >> 3, rr2 = lane & 7;
                uint2 bf[2][8];
                {
                    const uint2* bp = (const uint2*)wtb
                                    + ((size_t)(cm * 4) * ntglob + n0g) * 32 + lane;
#pragma unroll
                    for (int t = 0; t < 8; t++) bf[0][t] = __ldg(bp + t * 32);
                }
#pragma unroll
                for (int s = 0; s < 4; s++) {
                    if (s < 3) {
                        const uint2* bp = (const uint2*)wtb
                                        + ((size_t)(cm * 4 + s + 1) * ntglob + n0g) * 32 + lane;
#pragma unroll
                        for (int t = 0; t < 8; t++) bf[(s + 1) & 1][t] = __ldg(bp + t * 32);
                    }
                    uint32_t af[MTILES][4];
#pragma unroll
                    for (int mt = 0; mt < MTILES; mt++) {
                        int arow = wrow + mt * 16 + (j & 1) * 8 + rr2;
                        int acol = (s * 2 + (j >> 1)) ^ (arow & 7);
                        ldmatrix_x4(af[mt], Abase + (uint32_t)arow * 128
                                           + (uint32_t)acol * 16);
                    }
#pragma unroll
                    for (int t = 0; t < 8; t++)
#pragma unroll
                        for (int mt = 0; mt < MTILES; mt++)
                            mma16816(acc[mt][t], af[mt], bf[s & 1][t].x, bf[s & 1][t].y);
                }
            }
            __syncthreads();
        }
    }

    // ---------- final chunk MMA ----------
    {
        int cm = C - 1;
        uint32_t Abase = Ab0 + ((uint32_t)(cm & 1) << 14);
        int j = lane >> 3, rr2 = lane & 7;
#pragma unroll
        for (int s = 0; s < 4; s++) {
            uint32_t af[MTILES][4];
#pragma unroll
            for (int mt = 0; mt < MTILES; mt++) {
                int arow = wrow + mt * 16 + (j & 1) * 8 + rr2;
                int acol = (s * 2 + (j >> 1)) ^ (arow & 7);
                ldmatrix_x4(af[mt], Abase + (uint32_t)arow * 128
                                   + (uint32_t)acol * 16);
            }
            const uint2* bp = (const uint2*)wtb
                            + ((size_t)(cm * 4 + s) * ntglob + n0g) * 32 + lane;
            uint2 bf[8];
#pragma unroll
            for (int t = 0; t < 8; t++) bf[t] = __ldg(bp + t * 32);
#pragma unroll
            for (int t = 0; t < 8; t++)
#pragma unroll
                for (int mt = 0; mt < MTILES; mt++)
                    mma16816(acc[mt][t], af[mt], bf[t].x, bf[t].y);
        }
    }

    // ---------- epilogue ----------
#pragma unroll
    for (int mt = 0; mt < MTILES; mt++)
#pragma unroll
        for (int t = 0; t < 8; t++) {
            int gcol = n0 + wcol + t * 8 + (lane & 3) * 2;
            float2 bv = *(const float2*)&bb[gcol];
            int r0 = row0 + wrow + mt * 16 + (lane >> 2);
            float2 v0 = { acc[mt][t][0] + bv.x, acc[mt][t][1] + bv.y };
            float2 v1 = { acc[mt][t][2] + bv.x, acc[mt][t][3] + bv.y };
            *(float2*)&out[(size_t)r0 * fout + gcol]       = v0;
            *(float2*)&out[(size_t)(r0 + 8) * fout + gcol] = v1;
        }
}

// ---------------------------------------------------------------------------
// 4) BN batch stats
// ---------------------------------------------------------------------------
__global__ void bn_stats_kernel(const float* __restrict__ conv,
                                float* __restrict__ bn,
                                int N, int fout, int rows_per_block)
{
    __shared__ float r1[256];
    __shared__ float r2[256];
    int t   = threadIdx.x;
    int o   = t % fout;
    int rl  = t / fout;
    int rpb = 256 / fout;
    int n0  = blockIdx.x * rows_per_block;
    int n1  = min(N, n0 + rows_per_block);
    float s = 0.f, s2 = 0.f;
    for (int n = n0 + rl; n < n1; n += rpb) {
        float v = conv[(size_t)n * fout + o];
        s += v; s2 += v * v;
    }
    r1[t] = s; r2[t] = s2;
    __syncthreads();
    for (int off = 128; off >= fout; off >>= 1) {
        if (t < off) { r1[t] += r1[t + off]; r2[t] += r2[t + off]; }
        __syncthreads();
    }
    if (t < fout) {
        atomicAdd(&bn[t],        r1[t]);
        atomicAdd(&bn[fout + t], r2[t]);
    }
}

// ---------------------------------------------------------------------------
// 5) BN apply + ReLU + 2x2 maxpool, output NCHW
// ---------------------------------------------------------------------------
__global__ void bn_pool_kernel(const float* __restrict__ conv,
                               const float* __restrict__ bn,
                               const float* __restrict__ gamma,
                               const float* __restrict__ beta,
                               float* __restrict__ xout,
                               int B, int fout, int H, int W)
{
    int H2 = H >> 1, W2 = W >> 1;
    int idx = blockIdx.x * blockDim.x + threadIdx.x;
    int total = B * fout * H2 * W2;
    if (idx >= total) return;
    int o = idx % fout;
    int r = idx / fout;
    int w2 = r % W2; r /= W2;
    int h2 = r % H2;
    int b  = r / H2;

    float cnt  = (float)(B * H * W);
    float mean = bn[o] / cnt;
    float var  = bn[fout + o] / cnt - mean * mean;
    float sc   = gamma[o] * rsqrtf(var + 1e-5f);
    float sh   = beta[o] - mean * sc;

    int h = h2 * 2, w = w2 * 2;
    size_t base = ((size_t)(b * H + h) * W + w) * fout + o;
    float v00 = conv[base];
    float v01 = conv[base + fout];
    float v10 = conv[base + (size_t)W * fout];
    float v11 = conv[base + (size_t)W * fout + fout];
    float mx = fmaxf(fmaxf(fmaxf(v00 * sc + sh, 0.f), fmaxf(v01 * sc + sh, 0.f)),
                     fmaxf(fmaxf(v10 * sc + sh, 0.f), fmaxf(v11 * sc + sh, 0.f)));
    xout[((size_t)(b * fout + o) * H2 + h2) * W2 + w2] = mx;
}

// ---------------------------------------------------------------------------
extern "C" void kernel_launch(void* const* d_in, const int* in_sizes, int n_in,
                              void* d_out, int out_size)
{
    (void)in_sizes; (void)n_in; (void)out_size;

    float *pn, *sp, *conv, *x1, *x2, *bn;
    uint32_t* wtb;
    cudaGetSymbolAddress((void**)&pn,   g_pn);
    cudaGetSymbolAddress((void**)&sp,   g_sp);
    cudaGetSymbolAddress((void**)&wtb,  g_wtb);
    cudaGetSymbolAddress((void**)&conv, g_conv);
    cudaGetSymbolAddress((void**)&x1,   g_x1);
    cudaGetSymbolAddress((void**)&x2,   g_x2);
    cudaGetSymbolAddress((void**)&bn,   g_bn);

    const int SMEM = 1024 + 32768 + 8192 + 8192;
    cudaFuncSetAttribute(kan_mma_kernel<1>,
                         cudaFuncAttributeMaxDynamicSharedMemorySize, SMEM);
    cudaFuncSetAttribute(kan_mma_kernel<2>,
                         cudaFuncAttributeMaxDynamicSharedMemorySize, SMEM);

    struct LCfg { int B, C, H, W, fin, fout; };
    const LCfg L[3] = {
        {32,  16, 64, 64,  144,  64},
        {32,  64, 32, 32,  576, 128},
        {32, 128, 16, 16, 1152, 256},
    };

    const float* xin = (const float*)d_in[0];
    for (int l = 0; l < 3; l++) {
        const float* lnw = (const float*)d_in[1 + 7 * l + 0];
        const float* lnb = (const float*)d_in[1 + 7 * l + 1];
        const float* Wb  = (const float*)d_in[1 + 7 * l + 2];
        const float* bbv = (const float*)d_in[1 + 7 * l + 3];
        const float* Ws  = (const float*)d_in[1 + 7 * l + 4];
        const float* gam = (const float*)d_in[1 + 7 * l + 5];
        const float* bet = (const float*)d_in[1 + 7 * l + 6];

        int B = L[l].B, C = L[l].C, H = L[l].H, W = L[l].W;
        int fin = L[l].fin, fout = L[l].fout;
        int N = B * H * W;

        prep_kernel<<<(N + 7) / 8, 256>>>(xin, lnw, lnb, pn, sp, C, H, W, fin, N);

        int wtot = fin * 16 * fout;
        wtrans_frag_kernel<<<(wtot + 255) / 256, 256>>>(Wb, Ws, wtb, fin, fout);

        if (fout == 64) {
            dim3 g(N / 128, 1);
            kan_mma_kernel<1><<<g, 256, SMEM>>>(pn, sp, wtb, bbv, conv, fin, fout);
        } else {
            dim3 g(N / 128, fout / 128);
            kan_mma_kernel<2><<<g, 256, SMEM>>>(pn, sp, wtb, bbv, conv, fin, fout);
        }

        cudaMemsetAsync(bn, 0, 2 * fout * sizeof(float), 0);
        bn_stats_kernel<<<(N + 511) / 512, 256>>>(conv, bn, N, fout, 512);

        float* xout = (l == 0) ? x1 : (l == 1) ? x2 : (float*)d_out;
        int tot = B * fout * (H / 2) * (W / 2);
        bn_pool_kernel<<<(tot + 255) / 256, 256>>>(conv, bn, gam, bet, xout,
                                                   B, fout, H, W);
        xin = xout;
    }
}